// round 14
// baseline (speedup 1.0000x reference)
#include <cuda_runtime.h>
#include <cuda_fp16.h>
#include <cstdint>
#include <cstddef>

// ============================================================================
// QuaternionLinear == one dense GEMM: C[32768,1024] = X[32768,1024] @ W^T
//   W[4o+oc, 4i+ic] = S[oc][ic] * w_{T[oc][ic]}[o,i]
// compute_103 PTX rejects tcgen05.* -> cp.async + ldmatrix + mma.sync (HMMA).
// R14: R13 (fp32-direct A, W k-slot permutation, slot-XOR A layout, CTA
// 128x128, 128 thr, warp 64x64, 2 stages, ks frag ping-pong) + next-chunk
// cp.async issues interleaved under ks0/ks1 MMAs (off the critical path).
// ============================================================================

#define IN_F    1024
#define OUT_F   1024
#define M_TOTAL 32768

__device__ __half g_W[(size_t)OUT_F * IN_F];            // 2 MB (k-permuted)

__constant__ int   c_T[16] = {0,1,2,3,  1,0,3,2,  2,3,0,1,  3,2,1,0};
__constant__ float c_S[16] = {1,-1,-1,-1,  1,1,1,-1,  1,-1,1,1,  1,1,-1,1};

// W with per-k16-group column permutation: original column 16g+4t+u -> slot
// {2t+u (u<2) ; 2t+8+(u-2) (u>=2)}. A side feeds slots from contiguous x cols.
__global__ void build_w_kernel(const float* __restrict__ rw, const float* __restrict__ iw,
                               const float* __restrict__ jw, const float* __restrict__ kw) {
    int idx = blockIdx.x * 256 + threadIdx.x;   // idx = n*256 + i
    int n = idx >> 8;
    int i = idx & 255;                           // i = 4g + t
    int g = i >> 2, t = i & 3;
    int o = n >> 2, oc = n & 3;
    const float* ws[4] = {rw, iw, jw, kw};
    float v0 = c_S[oc*4+0] * ws[c_T[oc*4+0]][o*256 + i];
    float v1 = c_S[oc*4+1] * ws[c_T[oc*4+1]][o*256 + i];
    float v2 = c_S[oc*4+2] * ws[c_T[oc*4+2]][o*256 + i];
    float v3 = c_S[oc*4+3] * ws[c_T[oc*4+3]][o*256 + i];
    __half2 h01 = __floats2half2_rn(v0, v1);    // -> slots 2t, 2t+1
    __half2 h23 = __floats2half2_rn(v2, v3);    // -> slots 2t+8, 2t+9
    uint32_t* w32 = reinterpret_cast<uint32_t*>(g_W);
    w32[(size_t)n * 512 + 8 * g + t]     = *reinterpret_cast<uint32_t*>(&h01);
    w32[(size_t)n * 512 + 8 * g + t + 4] = *reinterpret_cast<uint32_t*>(&h23);
}

// --------------------------------------------------------------------------
// helpers
// --------------------------------------------------------------------------
__device__ __forceinline__ uint32_t smem_u32(const void* p) {
    uint32_t a;
    asm("{ .reg .u64 t; cvta.to.shared.u64 t, %1; cvt.u32.u64 %0, t; }" : "=r"(a) : "l"(p));
    return a;
}

__device__ __forceinline__ void cp_async16(uint32_t saddr, const void* gptr) {
    asm volatile("cp.async.cg.shared.global [%0], [%1], 16;" :: "r"(saddr), "l"(gptr));
}

#define CP_COMMIT() asm volatile("cp.async.commit_group;" ::: "memory")
#define CP_WAIT0()  asm volatile("cp.async.wait_group 0;" ::: "memory")

#define LDSM4(r, addr)                                                         \
    asm volatile("ldmatrix.sync.aligned.m8n8.x4.shared.b16 {%0,%1,%2,%3}, [%4];" \
                 : "=r"((r)[0]), "=r"((r)[1]), "=r"((r)[2]), "=r"((r)[3])       \
                 : "r"(addr))

#define MMA16816(c, a, b0, b1)                                                 \
    asm volatile("mma.sync.aligned.m16n8k16.row.col.f32.f16.f16.f32 "          \
                 "{%0,%1,%2,%3}, {%4,%5,%6,%7}, {%8,%9}, {%0,%1,%2,%3};"       \
                 : "+f"((c)[0]), "+f"((c)[1]), "+f"((c)[2]), "+f"((c)[3])      \
                 : "r"((a)[0]), "r"((a)[1]), "r"((a)[2]), "r"((a)[3]),         \
                   "r"(b0), "r"(b1))

__device__ __forceinline__ uint32_t swzB(uint32_t off) {   // fp16 128B rows
    return off ^ ((off >> 3) & 0x70u);
}

// --------------------------------------------------------------------------
// GEMM config: CTA 128x128, 128 threads, warp tile 64x64, BK=64, 2 stages
// A: fp32, 256B rows, 16B slots, slot ^= (row&1)*4  (bank-verified)
// --------------------------------------------------------------------------
constexpr int BM = 128, BN = 128, BK = 64;
constexpr int NCHUNK = IN_F / BK;          // 16
constexpr int ASTG = BM * BK * 4;          // 32768 B (fp32)
constexpr int BSTG = BN * BK * 2;          // 16384 B (fp16)
constexpr int SM_B    = 2 * ASTG;                    // 65536
constexpr int SM_BIAS = SM_B + 2 * BSTG;             // 98304
constexpr int SM_TOTAL = SM_BIAS + 512;              // 98816 -> 2 CTAs/SM

__global__ void __launch_bounds__(128, 2)
qgemm(const float* __restrict__ x, const float* __restrict__ bias,
      float* __restrict__ out) {
    extern __shared__ __align__(1024) char smem[];
    const uint32_t sb = smem_u32(smem);
    const int tid  = threadIdx.x;
    const int lane = tid & 31;
    const int wid  = tid >> 5;              // 0..3
    const int warp_m = wid >> 1;            // 0..1  (64 rows)
    const int warp_n = wid & 1;             // 0..1  (64 cols)
    const int m_base = blockIdx.y * BM;
    const int n_base = blockIdx.x * BN;

    reinterpret_cast<float*>(smem + SM_BIAS)[tid] = bias[n_base + tid];

    // cp.async geometry
    const int asegs = tid & 15;             // A: slot 0..15 per 256B row
    const int arow0 = tid >> 4;             // 0..7, 16 rounds of 8 rows
    const int aslot = asegs ^ ((arow0 & 1) * 4);   // row parity fixed per thread
    const int bseg  = tid & 7;              // B: 8 slots per 128B row
    const int brow0 = tid >> 3;             // 0..15, 8 rounds of 16 rows

    auto load_a_part = [&](int s, int c) {
        const float* ga = x + (size_t)(m_base + arow0) * IN_F + c * BK + asegs * 4;
        const uint32_t sA = sb + s * ASTG + (uint32_t)aslot * 16u;
        #pragma unroll
        for (int r = 0; r < 16; r++) {      // A: 128 rows fp32 (row step 8, parity const)
            cp_async16(sA + (uint32_t)(arow0 + r * 8) * 256u, ga + (size_t)(r * 8) * IN_F);
        }
    };
    auto load_b_part = [&](int s, int c) {
        const __half* gb = g_W + (size_t)(n_base + brow0) * IN_F + c * BK + bseg * 8;
        const uint32_t sB2 = sb + SM_B + s * BSTG;
        #pragma unroll
        for (int r = 0; r < 8; r++) {       // B: 128 rows fp16
            uint32_t off = swzB((uint32_t)(brow0 + r * 16) * 128u + (uint32_t)bseg * 16u);
            cp_async16(sB2 + off, gb + (size_t)(r * 16) * IN_F);
        }
    };

    // A read addressing: addr = rowbase[2mt+h] + kso[ks]
    const uint32_t apar = ((uint32_t)(lane >> 2) & 1u) * 64u;
    uint32_t rowbase[8];
    #pragma unroll
    for (int mt = 0; mt < 4; mt++) {
        uint32_t r = (uint32_t)(warp_m * 64 + mt * 16 + (lane >> 2));
        rowbase[2*mt]     = r * 256u + (uint32_t)(lane & 3) * 16u;
        rowbase[2*mt + 1] = rowbase[2*mt] + 8u * 256u;
    }
    uint32_t kso[4];
    #pragma unroll
    for (int ks = 0; ks < 4; ks++) kso[ks] = ((uint32_t)ks * 64u) ^ apar;

    float acc[4][8][4] = {};
    uint32_t afr[2][4][4], bfr[2][4][4];    // ks ping-pong fragments

    // A fragments: 2 LDS.128 + 4 cvt per mt (k-permutation -> contiguous float4)
    auto lda_ks = [&](const char* aB, int ks, int buf) {
        #pragma unroll
        for (int mt = 0; mt < 4; mt++) {
            float4 fr  = *reinterpret_cast<const float4*>(aB + rowbase[2*mt]     + kso[ks]);
            float4 fr8 = *reinterpret_cast<const float4*>(aB + rowbase[2*mt + 1] + kso[ks]);
            __half2 h0 = __floats2half2_rn(fr.x,  fr.y);
            __half2 h1 = __floats2half2_rn(fr8.x, fr8.y);
            __half2 h2 = __floats2half2_rn(fr.z,  fr.w);
            __half2 h3 = __floats2half2_rn(fr8.z, fr8.w);
            afr[buf][mt][0] = *reinterpret_cast<uint32_t*>(&h0);
            afr[buf][mt][1] = *reinterpret_cast<uint32_t*>(&h1);
            afr[buf][mt][2] = *reinterpret_cast<uint32_t*>(&h2);
            afr[buf][mt][3] = *reinterpret_cast<uint32_t*>(&h3);
        }
    };

    auto ldb_ks = [&](uint32_t sB2, int ks, int buf) {
        #pragma unroll
        for (int nt = 0; nt < 4; nt++) {
            int row = warp_n * 64 + nt * 16 + (lane & 7) + ((lane >> 4) & 1) * 8;
            int col = ks * 16 + ((lane >> 3) & 1) * 8;
            LDSM4(bfr[buf][nt], sB2 + swzB((uint32_t)row * 128u + (uint32_t)col * 2u));
        }
    };

    auto mma_all = [&](int buf) {
        #pragma unroll
        for (int mt = 0; mt < 4; mt++) {
            #pragma unroll
            for (int no = 0; no < 8; no++) {
                MMA16816(acc[mt][no], afr[buf][mt],
                         bfr[buf][no >> 1][(no & 1) * 2],
                         bfr[buf][no >> 1][(no & 1) * 2 + 1]);
            }
        }
    };

    load_a_part(0, 0);
    load_b_part(0, 0);
    CP_COMMIT();

    #pragma unroll 1
    for (int c = 0; c < NCHUNK; c++) {
        CP_WAIT0();          // chunk c resident (this thread's copies)
        __syncthreads();     // cross-thread visibility + stage (c+1)&1 free

        const int s = c & 1;
        const char* aB     = smem + s * ASTG;
        const uint32_t sB2 = sb + SM_B + s * BSTG;

        lda_ks(aB, 0, 0);
        ldb_ks(sB2, 0, 0);

        // ks0: prefetch ks1 frags, issue next-chunk A loads under MMAs
        lda_ks(aB, 1, 1);
        ldb_ks(sB2, 1, 1);
        if (c + 1 < NCHUNK) load_a_part(s ^ 1, c + 1);
        mma_all(0);

        // ks1: prefetch ks2 frags, issue next-chunk B loads + commit
        lda_ks(aB, 2, 0);
        ldb_ks(sB2, 2, 0);
        if (c + 1 < NCHUNK) load_b_part(s ^ 1, c + 1);
        CP_COMMIT();         // unconditional: uniform group counting
        mma_all(1);

        // ks2: prefetch ks3 frags
        lda_ks(aB, 3, 1);
        ldb_ks(sB2, 3, 1);
        mma_all(0);

        // ks3
        mma_all(1);
    }

    // epilogue: direct float2 stores + bias
    const float* sbias = reinterpret_cast<const float*>(smem + SM_BIAS);
    #pragma unroll
    for (int mt = 0; mt < 4; mt++) {
        int r0 = m_base + warp_m * 64 + mt * 16 + (lane >> 2);
        #pragma unroll
        for (int no = 0; no < 8; no++) {
            int cl = warp_n * 64 + no * 8 + (lane & 3) * 2;   // local col
            float b0 = sbias[cl], b1 = sbias[cl + 1];
            float2 v0 = make_float2(acc[mt][no][0] + b0, acc[mt][no][1] + b1);
            float2 v1 = make_float2(acc[mt][no][2] + b0, acc[mt][no][3] + b1);
            *reinterpret_cast<float2*>(out + (size_t)r0 * OUT_F + n_base + cl)       = v0;
            *reinterpret_cast<float2*>(out + (size_t)(r0 + 8) * OUT_F + n_base + cl) = v1;
        }
    }
}

// --------------------------------------------------------------------------
extern "C" void kernel_launch(void* const* d_in, const int* in_sizes, int n_in,
                              void* d_out, int out_size) {
    const float* x    = (const float*)d_in[0];
    const float* rw   = (const float*)d_in[1];
    const float* iw   = (const float*)d_in[2];
    const float* jw   = (const float*)d_in[3];
    const float* kw   = (const float*)d_in[4];
    const float* bias = (const float*)d_in[5];
    float* out = (float*)d_out;

    static bool attr_done = false;
    if (!attr_done) {
        cudaFuncSetAttribute(qgemm, cudaFuncAttributeMaxDynamicSharedMemorySize, SM_TOTAL);
        attr_done = true;
    }

    build_w_kernel<<<OUT_F * 256 / 256, 256>>>(rw, iw, jw, kw);

    dim3 grid(OUT_F / BN, M_TOTAL / BM);   // (8, 256): N fastest -> A-tile L2 reuse
    qgemm<<<grid, 128, SM_TOTAL>>>(x, bias, out);
}

// round 15
// speedup vs baseline: 1.1507x; 1.1507x over previous
#include <cuda_runtime.h>
#include <cuda_fp16.h>
#include <cstdint>
#include <cstddef>

// ============================================================================
// QuaternionLinear == one dense GEMM: C[32768,1024] = X[32768,1024] @ W^T
//   W[4o+oc, 4i+ic] = S[oc][ic] * w_{T[oc][ic]}[o,i]
// compute_103 PTX rejects tcgen05.* -> cp.async + ldmatrix + mma.sync (HMMA).
// R15: R13 exactly (fp32-direct A, W k-slot permutation, slot-XOR A layout,
// CTA 128x128, 128 thr, warp 64x64, 2 stages, ks frag ping-pong) with ONE
// change: post-barrier order is ks0-fragment loads FIRST, then the 24
// next-chunk cp.async issues -- the LSU burst now covers the LDS latency
// instead of delaying the first MMA.
// ============================================================================

#define IN_F    1024
#define OUT_F   1024
#define M_TOTAL 32768

__device__ __half g_W[(size_t)OUT_F * IN_F];            // 2 MB (k-permuted)

__constant__ int   c_T[16] = {0,1,2,3,  1,0,3,2,  2,3,0,1,  3,2,1,0};
__constant__ float c_S[16] = {1,-1,-1,-1,  1,1,1,-1,  1,-1,1,1,  1,1,-1,1};

// W with per-k16-group column permutation: original column 16g+4t+u -> slot
// {2t+u (u<2) ; 2t+8+(u-2) (u>=2)}. A side feeds slots from contiguous x cols.
__global__ void build_w_kernel(const float* __restrict__ rw, const float* __restrict__ iw,
                               const float* __restrict__ jw, const float* __restrict__ kw) {
    int idx = blockIdx.x * 256 + threadIdx.x;   // idx = n*256 + i
    int n = idx >> 8;
    int i = idx & 255;                           // i = 4g + t
    int g = i >> 2, t = i & 3;
    int o = n >> 2, oc = n & 3;
    const float* ws[4] = {rw, iw, jw, kw};
    float v0 = c_S[oc*4+0] * ws[c_T[oc*4+0]][o*256 + i];
    float v1 = c_S[oc*4+1] * ws[c_T[oc*4+1]][o*256 + i];
    float v2 = c_S[oc*4+2] * ws[c_T[oc*4+2]][o*256 + i];
    float v3 = c_S[oc*4+3] * ws[c_T[oc*4+3]][o*256 + i];
    __half2 h01 = __floats2half2_rn(v0, v1);    // -> slots 2t, 2t+1
    __half2 h23 = __floats2half2_rn(v2, v3);    // -> slots 2t+8, 2t+9
    uint32_t* w32 = reinterpret_cast<uint32_t*>(g_W);
    w32[(size_t)n * 512 + 8 * g + t]     = *reinterpret_cast<uint32_t*>(&h01);
    w32[(size_t)n * 512 + 8 * g + t + 4] = *reinterpret_cast<uint32_t*>(&h23);
}

// --------------------------------------------------------------------------
// helpers
// --------------------------------------------------------------------------
__device__ __forceinline__ uint32_t smem_u32(const void* p) {
    uint32_t a;
    asm("{ .reg .u64 t; cvta.to.shared.u64 t, %1; cvt.u32.u64 %0, t; }" : "=r"(a) : "l"(p));
    return a;
}

__device__ __forceinline__ void cp_async16(uint32_t saddr, const void* gptr) {
    asm volatile("cp.async.cg.shared.global [%0], [%1], 16;" :: "r"(saddr), "l"(gptr));
}

#define CP_COMMIT() asm volatile("cp.async.commit_group;" ::: "memory")
#define CP_WAIT0()  asm volatile("cp.async.wait_group 0;" ::: "memory")

#define LDSM4(r, addr)                                                         \
    asm volatile("ldmatrix.sync.aligned.m8n8.x4.shared.b16 {%0,%1,%2,%3}, [%4];" \
                 : "=r"((r)[0]), "=r"((r)[1]), "=r"((r)[2]), "=r"((r)[3])       \
                 : "r"(addr))

#define MMA16816(c, a, b0, b1)                                                 \
    asm volatile("mma.sync.aligned.m16n8k16.row.col.f32.f16.f16.f32 "          \
                 "{%0,%1,%2,%3}, {%4,%5,%6,%7}, {%8,%9}, {%0,%1,%2,%3};"       \
                 : "+f"((c)[0]), "+f"((c)[1]), "+f"((c)[2]), "+f"((c)[3])      \
                 : "r"((a)[0]), "r"((a)[1]), "r"((a)[2]), "r"((a)[3]),         \
                   "r"(b0), "r"(b1))

__device__ __forceinline__ uint32_t swzB(uint32_t off) {   // fp16 128B rows
    return off ^ ((off >> 3) & 0x70u);
}

// --------------------------------------------------------------------------
// GEMM config: CTA 128x128, 128 threads, warp tile 64x64, BK=64, 2 stages
// A: fp32, 256B rows, 16B slots, slot ^= (row&1)*4  (bank-verified)
// --------------------------------------------------------------------------
constexpr int BM = 128, BN = 128, BK = 64;
constexpr int NCHUNK = IN_F / BK;          // 16
constexpr int ASTG = BM * BK * 4;          // 32768 B (fp32)
constexpr int BSTG = BN * BK * 2;          // 16384 B (fp16)
constexpr int SM_B    = 2 * ASTG;                    // 65536
constexpr int SM_BIAS = SM_B + 2 * BSTG;             // 98304
constexpr int SM_TOTAL = SM_BIAS + 512;              // 98816 -> 2 CTAs/SM

__global__ void __launch_bounds__(128, 2)
qgemm(const float* __restrict__ x, const float* __restrict__ bias,
      float* __restrict__ out) {
    extern __shared__ __align__(1024) char smem[];
    const uint32_t sb = smem_u32(smem);
    const int tid  = threadIdx.x;
    const int lane = tid & 31;
    const int wid  = tid >> 5;              // 0..3
    const int warp_m = wid >> 1;            // 0..1  (64 rows)
    const int warp_n = wid & 1;             // 0..1  (64 cols)
    const int m_base = blockIdx.y * BM;
    const int n_base = blockIdx.x * BN;

    reinterpret_cast<float*>(smem + SM_BIAS)[tid] = bias[n_base + tid];

    // cp.async geometry
    const int asegs = tid & 15;             // A: slot 0..15 per 256B row
    const int arow0 = tid >> 4;             // 0..7, 16 rounds of 8 rows
    const int aslot = asegs ^ ((arow0 & 1) * 4);   // row parity fixed per thread
    const int bseg  = tid & 7;              // B: 8 slots per 128B row
    const int brow0 = tid >> 3;             // 0..15, 8 rounds of 16 rows

    auto load_chunk = [&](int s, int c) {
        const int k0 = c * BK;
        const float*  ga = x + (size_t)(m_base + arow0) * IN_F + k0 + asegs * 4;
        const __half* gb = g_W + (size_t)(n_base + brow0) * IN_F + k0 + bseg * 8;
        const uint32_t sA  = sb + s * ASTG + (uint32_t)aslot * 16u;
        const uint32_t sB2 = sb + SM_B + s * BSTG;
        #pragma unroll
        for (int r = 0; r < 16; r++) {      // A: 128 rows fp32 (row step 8, parity const)
            cp_async16(sA + (uint32_t)(arow0 + r * 8) * 256u, ga + (size_t)(r * 8) * IN_F);
        }
        #pragma unroll
        for (int r = 0; r < 8; r++) {       // B: 128 rows fp16
            uint32_t off = swzB((uint32_t)(brow0 + r * 16) * 128u + (uint32_t)bseg * 16u);
            cp_async16(sB2 + off, gb + (size_t)(r * 16) * IN_F);
        }
    };

    // A read addressing: addr = rowbase[2mt+h] + kso[ks]
    const uint32_t apar = ((uint32_t)(lane >> 2) & 1u) * 64u;
    uint32_t rowbase[8];
    #pragma unroll
    for (int mt = 0; mt < 4; mt++) {
        uint32_t r = (uint32_t)(warp_m * 64 + mt * 16 + (lane >> 2));
        rowbase[2*mt]     = r * 256u + (uint32_t)(lane & 3) * 16u;
        rowbase[2*mt + 1] = rowbase[2*mt] + 8u * 256u;
    }
    uint32_t kso[4];
    #pragma unroll
    for (int ks = 0; ks < 4; ks++) kso[ks] = ((uint32_t)ks * 64u) ^ apar;

    float acc[4][8][4] = {};
    uint32_t afr[2][4][4], bfr[2][4][4];    // ks ping-pong fragments

    // A fragments: 2 LDS.128 + 4 cvt per mt (k-permutation -> contiguous float4)
    auto lda_ks = [&](const char* aB, int ks, int buf) {
        #pragma unroll
        for (int mt = 0; mt < 4; mt++) {
            float4 fr  = *reinterpret_cast<const float4*>(aB + rowbase[2*mt]     + kso[ks]);
            float4 fr8 = *reinterpret_cast<const float4*>(aB + rowbase[2*mt + 1] + kso[ks]);
            __half2 h0 = __floats2half2_rn(fr.x,  fr.y);
            __half2 h1 = __floats2half2_rn(fr8.x, fr8.y);
            __half2 h2 = __floats2half2_rn(fr.z,  fr.w);
            __half2 h3 = __floats2half2_rn(fr8.z, fr8.w);
            afr[buf][mt][0] = *reinterpret_cast<uint32_t*>(&h0);
            afr[buf][mt][1] = *reinterpret_cast<uint32_t*>(&h1);
            afr[buf][mt][2] = *reinterpret_cast<uint32_t*>(&h2);
            afr[buf][mt][3] = *reinterpret_cast<uint32_t*>(&h3);
        }
    };

    auto ldb_ks = [&](uint32_t sB2, int ks, int buf) {
        #pragma unroll
        for (int nt = 0; nt < 4; nt++) {
            int row = warp_n * 64 + nt * 16 + (lane & 7) + ((lane >> 4) & 1) * 8;
            int col = ks * 16 + ((lane >> 3) & 1) * 8;
            LDSM4(bfr[buf][nt], sB2 + swzB((uint32_t)row * 128u + (uint32_t)col * 2u));
        }
    };

    load_chunk(0, 0);
    CP_COMMIT();

    #pragma unroll 1
    for (int c = 0; c < NCHUNK; c++) {
        CP_WAIT0();          // chunk c resident
        __syncthreads();     // cross-thread visibility + stage (c+1)&1 free

        const int s = c & 1;
        const char* aB     = smem + s * ASTG;
        const uint32_t sB2 = sb + SM_B + s * BSTG;

        // ks0 fragments FIRST -- their LDS latency is covered by the cp.async
        // issue burst that follows (instead of being delayed by it).
        lda_ks(aB, 0, 0);
        ldb_ks(sB2, 0, 0);

        if (c + 1 < NCHUNK) { load_chunk((c + 1) & 1, c + 1); }
        CP_COMMIT();         // unconditional: uniform group counting

        #pragma unroll
        for (int ks = 0; ks < 4; ks++) {
            const int cur = ks & 1;
            if (ks < 3) {                     // prefetch next fragments
                lda_ks(aB, ks + 1, cur ^ 1);
                ldb_ks(sB2, ks + 1, cur ^ 1);
            }
            #pragma unroll
            for (int mt = 0; mt < 4; mt++) {
                #pragma unroll
                for (int no = 0; no < 8; no++) {
                    MMA16816(acc[mt][no], afr[cur][mt],
                             bfr[cur][no >> 1][(no & 1) * 2],
                             bfr[cur][no >> 1][(no & 1) * 2 + 1]);
                }
            }
        }
    }

    // epilogue: direct float2 stores + bias
    const float* sbias = reinterpret_cast<const float*>(smem + SM_BIAS);
    #pragma unroll
    for (int mt = 0; mt < 4; mt++) {
        int r0 = m_base + warp_m * 64 + mt * 16 + (lane >> 2);
        #pragma unroll
        for (int no = 0; no < 8; no++) {
            int cl = warp_n * 64 + no * 8 + (lane & 3) * 2;   // local col
            float b0 = sbias[cl], b1 = sbias[cl + 1];
            float2 v0 = make_float2(acc[mt][no][0] + b0, acc[mt][no][1] + b1);
            float2 v1 = make_float2(acc[mt][no][2] + b0, acc[mt][no][3] + b1);
            *reinterpret_cast<float2*>(out + (size_t)r0 * OUT_F + n_base + cl)       = v0;
            *reinterpret_cast<float2*>(out + (size_t)(r0 + 8) * OUT_F + n_base + cl) = v1;
        }
    }
}

// --------------------------------------------------------------------------
extern "C" void kernel_launch(void* const* d_in, const int* in_sizes, int n_in,
                              void* d_out, int out_size) {
    const float* x    = (const float*)d_in[0];
    const float* rw   = (const float*)d_in[1];
    const float* iw   = (const float*)d_in[2];
    const float* jw   = (const float*)d_in[3];
    const float* kw   = (const float*)d_in[4];
    const float* bias = (const float*)d_in[5];
    float* out = (float*)d_out;

    static bool attr_done = false;
    if (!attr_done) {
        cudaFuncSetAttribute(qgemm, cudaFuncAttributeMaxDynamicSharedMemorySize, SM_TOTAL);
        attr_done = true;
    }

    build_w_kernel<<<OUT_F * 256 / 256, 256>>>(rw, iw, jw, kw);

    dim3 grid(OUT_F / BN, M_TOTAL / BM);   // (8, 256): N fastest -> A-tile L2 reuse
    qgemm<<<grid, 128, SM_TOTAL>>>(x, bias, out);
}